// round 8
// baseline (speedup 1.0000x reference)
#include <cuda_runtime.h>
#include <cuda_bf16.h>
#include <float.h>

#define NUM_CLASSES 16
#define N_BOX 2048
#define MAXC 256            // max candidates per (image,class); observed ~122 +/- 11
#define NWORD 4             // MAXC/64 suppression-mask words
#define TPB 256
#define MAX_PER_CLASS 100
#define MAX_DET 100
#define NCAND (NUM_CLASSES * MAX_PER_CLASS)  // 1600
#define SCORE_TH 0.05f
#define IOU_TH 0.5f

// Scratch (B=4): per-class kept candidates as packed sort keys + boxes.
//   key = (float_bits(score) << 32) | (0xFFFFFFFF - tag)
// Valid scores > 0 -> float bit pattern preserves order; ~tag breaks ties
// ascending. Each class's 100-slot list is STRICTLY DESCENDING.
__device__ unsigned long long g_key[4 * NCAND];
__device__ float4             g_box[4 * NCAND];
__device__ int                g_cnt[4 * NUM_CLASSES];
// Per-image arrival counters (replay-safe: finisher resets to 0).
__device__ unsigned g_done[4] = {0, 0, 0, 0};

__global__ void __launch_bounds__(TPB)
nms_fused_kernel(const float* __restrict__ pred, float* __restrict__ out, int B) {
    const int task = blockIdx.x;
    const int b = task >> 4;
    const int c = task & 15;
    const int tid = threadIdx.x;
    const int lane = tid & 31;

    __shared__ union {
        struct {
            unsigned long long key[MAXC];          // unsorted keys
            unsigned long long skey[MAXC];         // rank-sorted keys
            float4             box[MAXC];          // boxes in sorted order
            unsigned long long mask[MAXC][NWORD];  // suppression bitmask
        } a;                                       // 16.4 KB (phase A)
        unsigned long long merge_key[NCAND];       // 12.8 KB (merge)
    } s;
    __shared__ int s_cnt, s_nkeep, s_ticket;
    __shared__ int s_keep[MAX_PER_CLASS];

    if (tid == 0) s_cnt = 0;

    // ---- filter: prefetch ALL (cls,score) pairs first (MLP=8), then ballot
    //      compaction with one shared atomic per warp-round ----
    const float* base = pred + (size_t)b * N_BOX * 6;
    const float2* cs = (const float2*)base;       // (cls,score) at float2 idx 3n+2
    const float fc = (float)c;
    float2 v[8];
    #pragma unroll
    for (int k = 0; k < 8; ++k)
        v[k] = cs[3 * (tid + k * TPB) + 2];       // independent, front-batched

    __syncthreads();                              // s_cnt=0 visible

    #pragma unroll
    for (int k = 0; k < 8; ++k) {
        const int n = tid + k * TPB;
        const bool hit = (v[k].x == fc) & (v[k].y > SCORE_TH);
        const unsigned m = __ballot_sync(0xffffffffu, hit);
        if (m) {
            const int lead = __ffs(m) - 1;
            int basepos = 0;
            if (lane == lead) basepos = atomicAdd(&s_cnt, __popc(m));
            basepos = __shfl_sync(0xffffffffu, basepos, lead);
            if (hit) {
                const int slot = basepos + __popc(m & ((1u << lane) - 1u));
                if (slot < MAXC)
                    s.a.key[slot] = ((unsigned long long)__float_as_uint(v[k].y) << 32)
                                  | (unsigned long long)(0xFFFFFFFFu - (unsigned)n);
            }
        }
    }
    __syncthreads();
    const int M = min(s_cnt, MAXC);

    // ---- rank sort + fused box gather: position = # keys greater ----
    for (int i = tid; i < M; i += TPB) {
        const unsigned long long ki = s.a.key[i];
        int r = 0;
        #pragma unroll 4
        for (int j = 0; j < M; ++j) r += (s.a.key[j] > ki);
        const int n = (int)(0xFFFFFFFFu - (unsigned)(ki & 0xFFFFFFFFull));
        const float2* p = (const float2*)(base + n * 6);
        const float2 p0 = p[0], p1 = p[1];
        s.a.skey[r] = ki;
        s.a.box[r]  = make_float4(p0.x, p0.y, p1.x, p1.y);
    }
    __syncthreads();

    // ---- suppression bitmask over (i, word) pairs ----
    const int NW = (M + 63) >> 6;
    for (int item = tid; item < M * NW; item += TPB) {
        const int i = item / NW;
        const int w = item - i * NW;
        const float4 bi = s.a.box[i];
        const float areai = (bi.z - bi.x) * (bi.w - bi.y);
        unsigned long long bits = 0ULL;
        const int j0 = w << 6;
        const int jend = min(j0 + 64, M);
        for (int j = (j0 > i + 1 ? j0 : i + 1); j < jend; ++j) {
            const float4 bj = s.a.box[j];
            float iw = fminf(bi.z, bj.z) - fmaxf(bi.x, bj.x);
            float ih = fminf(bi.w, bj.w) - fmaxf(bi.y, bj.y);
            iw = fmaxf(iw, 0.f);
            ih = fmaxf(ih, 0.f);
            const float inter = iw * ih;
            if (inter > 0.f) {
                const float areaj = (bj.z - bj.x) * (bj.w - bj.y);
                const float uni = areai + areaj - inter;
                if (inter / fmaxf(uni, 1e-8f) > IOU_TH)
                    bits |= 1ULL << (j - j0);
            }
        }
        s.a.mask[i][w] = bits;
    }
    __syncthreads();

    // ---- greedy sweep on tid 0 (hoisted loads), OVERLAPPED with tag-tail
    //      writes to g_key by the other warps ----
    if (tid == 0) {
        unsigned long long remv0 = 0, remv1 = 0, remv2 = 0, remv3 = 0;
        int nk = 0;
        for (int i = 0; i < M; ++i) {
            const unsigned long long m0 = s.a.mask[i][0];
            const unsigned long long m1 = s.a.mask[i][1];
            const unsigned long long m2 = s.a.mask[i][2];
            const unsigned long long m3 = s.a.mask[i][3];
            const unsigned long long rw = (i < 64) ? remv0 : (i < 128) ? remv1
                                        : (i < 192) ? remv2 : remv3;
            if (!((rw >> (i & 63)) & 1ULL)) {
                if (nk < MAX_PER_CLASS) s_keep[nk] = i;
                nk++;
                remv0 |= m0; remv1 |= m1; remv2 |= m2; remv3 |= m3;
            }
        }
        const int nkeep = min(nk, MAX_PER_CLASS);
        s_nkeep = nkeep;
        g_cnt[task] = nkeep;
    } else if (tid >= 32) {
        // pre-write ALL 100 slots as invalid tags; real entries overwrite below
        for (int k = tid - 32; k < MAX_PER_CLASS; k += TPB - 32) {
            const int gid = c * MAX_PER_CLASS + k;
            g_key[b * NCAND + gid] =
                (unsigned long long)(0xFFFFFFFFu - (unsigned)gid);
        }
    }
    __syncthreads();

    // ---- emit kept entries (overwrite tags for k < nkeep) ----
    const int nkeep = s_nkeep;
    for (int k = tid; k < nkeep; k += TPB) {
        const int gid = c * MAX_PER_CLASS + k;
        const int i = s_keep[k];
        g_key[b * NCAND + gid] = (s.a.skey[i] & 0xFFFFFFFF00000000ull)
                               | (unsigned long long)(0xFFFFFFFFu - (unsigned)gid);
        g_box[b * NCAND + gid] = s.a.box[i];
    }

    // ---- arrive: last of this image's 16 blocks does the merge; rest exit ----
    __threadfence();      // release our g_key/g_box/g_cnt writes
    __syncthreads();      // all threads' writes issued before arrival
    if (tid == 0) s_ticket = (int)atomicAdd(&g_done[b], 1);
    __syncthreads();
    if (s_ticket != NUM_CLASSES - 1) return;   // 60 of 64 blocks exit here

    // ================= MERGE (one block per image) =================
    if (tid == 0) atomicExch(&g_done[b], 0);   // reset for next graph replay
    __threadfence();                            // acquire: order reads below

    // zero this image's output rows (scatter below fills valid ranks)
    for (int i = tid; i < MAX_DET * 6; i += TPB)
        out[(size_t)b * MAX_DET * 6 + i] = 0.f;

    for (int i = tid; i < NCAND; i += TPB)
        s.merge_key[i] = __ldcg(&g_key[b * NCAND + i]);
    __syncthreads();

    for (int cand = tid; cand < NCAND; cand += TPB) {
        const unsigned long long myk = s.merge_key[cand];
        const float sc = __uint_as_float((unsigned)(myk >> 32));
        if (sc <= SCORE_TH) continue;          // invalid tag slot
        const int cc0 = cand / MAX_PER_CLASS;
        int rank = cand - cc0 * MAX_PER_CLASS; // own class: exactly k greater
        // 15 binary searches; early exit once rank >= 100 (rank is monotone)
        #pragma unroll 4
        for (int cc = 0; cc < NUM_CLASSES; ++cc) {
            if (cc == cc0) continue;
            const unsigned long long* arr = s.merge_key + cc * MAX_PER_CLASS;
            int lo = 0, len = MAX_PER_CLASS;
            while (len > 0) {
                const int half = len >> 1;
                if (arr[lo + half] > myk) { lo += half + 1; len -= half + 1; }
                else                      { len = half; }
            }
            rank += lo;
            if (rank >= MAX_DET) break;
        }
        if (rank < MAX_DET) {
            const float4 bx = __ldcg(&g_box[b * NCAND + cand]);
            float* o = out + ((size_t)b * MAX_DET + rank) * 6;
            o[0] = bx.x; o[1] = bx.y; o[2] = bx.z; o[3] = bx.w;
            o[4] = (float)cc0;
            o[5] = sc;
        }
    }

    if (tid == 0) {
        int sum = 0;
        #pragma unroll
        for (int i = 0; i < NUM_CLASSES; ++i)
            sum += __ldcg(&g_cnt[b * NUM_CLASSES + i]);
        out[(size_t)B * MAX_DET * 6 + b] = (float)min(sum, MAX_DET);
    }
}

extern "C" void kernel_launch(void* const* d_in, const int* in_sizes, int n_in,
                              void* d_out, int out_size) {
    const float* pred = (const float*)d_in[0];
    int B = in_sizes[0] / (N_BOX * 6);  // expected 4
    nms_fused_kernel<<<B * NUM_CLASSES, TPB>>>(pred, (float*)d_out, B);
}

// round 9
// speedup vs baseline: 1.3454x; 1.3454x over previous
#include <cuda_runtime.h>
#include <cuda_bf16.h>
#include <float.h>

#define NUM_CLASSES 16
#define N_BOX 2048
#define MAXC 256            // max candidates per (image,class); observed ~122 +/- 11
#define NWORD 4             // MAXC/64 suppression-mask words
#define TPB 256
#define MAX_PER_CLASS 100
#define MAX_DET 100
#define NCAND (NUM_CLASSES * MAX_PER_CLASS)  // 1600
#define SCORE_TH 0.05f
#define IOU_TH 0.5f

// Scratch (B=4): per-class kept keys only (boxes stay in shared per-block).
//   key = (float_bits(score) << 32) | (0xFFFFFFFF - tag)
// Valid scores > 0 -> float bit pattern preserves order; ~tag breaks ties
// ascending. Each class's 100-slot list is STRICTLY DESCENDING.
__device__ unsigned long long g_key[4 * NCAND];
__device__ int                g_cnt[4 * NUM_CLASSES];

// Grid barrier (replay-safe: count returns to 0 each launch, gen monotone).
__device__ unsigned g_bar_count = 0;
__device__ unsigned g_bar_gen   = 0;

__global__ void __launch_bounds__(TPB)
nms_fused_kernel(const float* __restrict__ pred, float* __restrict__ out, int B) {
    const int task = blockIdx.x;
    const int b = task >> 4;
    const int c = task & 15;
    const int tid = threadIdx.x;
    const int lane = tid & 31;

    __shared__ float4 s_box[MAXC];                 // sorted boxes (phase A), 4 KB
    __shared__ float4 s_kept_box[MAX_PER_CLASS];   // compacted kept boxes, 1.6 KB
    __shared__ union {
        struct {
            unsigned long long key[MAXC];          // unsorted keys   (2 KB)
            unsigned long long skey[MAXC];         // sorted keys     (2 KB)
            unsigned long long mask[MAXC][NWORD];  // suppr. bitmask  (8 KB)
        } a;
        unsigned long long merge_key[NCAND];       // phase B, 12.8 KB
    } s;
    __shared__ int s_cnt, s_nkeep;
    __shared__ int s_keep[MAX_PER_CLASS];

    if (tid == 0) s_cnt = 0;
    // Zero this image's output rows (one block per image). Ordered before the
    // phase-B scatter writes by the grid barrier.
    if (c == 0) {
        for (int i = tid; i < MAX_DET * 6; i += TPB)
            out[(size_t)b * MAX_DET * 6 + i] = 0.f;
    }

    // ---- filter: prefetch ALL (cls,score) pairs first (MLP=8), then ballot
    //      compaction with one shared atomic per warp-round ----
    const float* base = pred + (size_t)b * N_BOX * 6;
    const float2* cs = (const float2*)base;       // (cls,score) at float2 idx 3n+2
    const float fc = (float)c;
    float2 v[8];
    #pragma unroll
    for (int k = 0; k < 8; ++k)
        v[k] = cs[3 * (tid + k * TPB) + 2];       // independent, front-batched

    __syncthreads();                              // s_cnt=0 visible

    #pragma unroll
    for (int k = 0; k < 8; ++k) {
        const int n = tid + k * TPB;
        const bool hit = (v[k].x == fc) & (v[k].y > SCORE_TH);
        const unsigned m = __ballot_sync(0xffffffffu, hit);
        if (m) {
            const int lead = __ffs(m) - 1;
            int basepos = 0;
            if (lane == lead) basepos = atomicAdd(&s_cnt, __popc(m));
            basepos = __shfl_sync(0xffffffffu, basepos, lead);
            if (hit) {
                const int slot = basepos + __popc(m & ((1u << lane) - 1u));
                if (slot < MAXC)
                    s.a.key[slot] = ((unsigned long long)__float_as_uint(v[k].y) << 32)
                                  | (unsigned long long)(0xFFFFFFFFu - (unsigned)n);
            }
        }
    }
    __syncthreads();
    const int M = min(s_cnt, MAXC);

    // ---- rank sort + fused box gather: position = # keys greater ----
    for (int i = tid; i < M; i += TPB) {
        const unsigned long long ki = s.a.key[i];
        int r = 0;
        #pragma unroll 4
        for (int j = 0; j < M; ++j) r += (s.a.key[j] > ki);
        const int n = (int)(0xFFFFFFFFu - (unsigned)(ki & 0xFFFFFFFFull));
        const float2* p = (const float2*)(base + n * 6);
        const float2 p0 = p[0], p1 = p[1];
        s.a.skey[r] = ki;
        s_box[r]    = make_float4(p0.x, p0.y, p1.x, p1.y);
    }
    __syncthreads();

    // ---- suppression bitmask over (i, word) pairs ----
    const int NW = (M + 63) >> 6;
    for (int item = tid; item < M * NW; item += TPB) {
        const int i = item / NW;
        const int w = item - i * NW;
        const float4 bi = s_box[i];
        const float areai = (bi.z - bi.x) * (bi.w - bi.y);
        unsigned long long bits = 0ULL;
        const int j0 = w << 6;
        const int jend = min(j0 + 64, M);
        for (int j = (j0 > i + 1 ? j0 : i + 1); j < jend; ++j) {
            const float4 bj = s_box[j];
            float iw = fminf(bi.z, bj.z) - fmaxf(bi.x, bj.x);
            float ih = fminf(bi.w, bj.w) - fmaxf(bi.y, bj.y);
            iw = fmaxf(iw, 0.f);
            ih = fmaxf(ih, 0.f);
            const float inter = iw * ih;
            if (inter > 0.f) {
                const float areaj = (bj.z - bj.x) * (bj.w - bj.y);
                const float uni = areai + areaj - inter;
                if (inter / fmaxf(uni, 1e-8f) > IOU_TH)
                    bits |= 1ULL << (j - j0);
            }
        }
        s.a.mask[i][w] = bits;
    }
    __syncthreads();

    // ---- greedy sweep on tid 0 (hoisted loads), OVERLAPPED with tag-tail
    //      writes to g_key by the other warps ----
    if (tid == 0) {
        unsigned long long remv0 = 0, remv1 = 0, remv2 = 0, remv3 = 0;
        int nk = 0;
        for (int i = 0; i < M; ++i) {
            const unsigned long long m0 = s.a.mask[i][0];
            const unsigned long long m1 = s.a.mask[i][1];
            const unsigned long long m2 = s.a.mask[i][2];
            const unsigned long long m3 = s.a.mask[i][3];
            const unsigned long long rw = (i < 64) ? remv0 : (i < 128) ? remv1
                                        : (i < 192) ? remv2 : remv3;
            if (!((rw >> (i & 63)) & 1ULL)) {
                if (nk < MAX_PER_CLASS) s_keep[nk] = i;
                nk++;
                remv0 |= m0; remv1 |= m1; remv2 |= m2; remv3 |= m3;
            }
        }
        const int nkeep = min(nk, MAX_PER_CLASS);
        s_nkeep = nkeep;
        g_cnt[task] = nkeep;
    } else if (tid >= 32) {
        // pre-write ALL 100 slots as invalid tags; kept entries overwrite below
        for (int k = tid - 32; k < MAX_PER_CLASS; k += TPB - 32) {
            const int gid = c * MAX_PER_CLASS + k;
            g_key[b * NCAND + gid] =
                (unsigned long long)(0xFFFFFFFFu - (unsigned)gid);
        }
    }
    __syncthreads();

    // ---- emit kept keys (global) + compact kept boxes into shared ----
    const int nkeep = s_nkeep;
    for (int k = tid; k < nkeep; k += TPB) {
        const int gid = c * MAX_PER_CLASS + k;
        const int i = s_keep[k];
        g_key[b * NCAND + gid] = (s.a.skey[i] & 0xFFFFFFFF00000000ull)
                               | (unsigned long long)(0xFFFFFFFFu - (unsigned)gid);
        s_kept_box[k] = s_box[i];     // stays in shared across the barrier
    }

    // ================= GRID BARRIER (64 co-resident blocks) =================
    __threadfence();
    __syncthreads();
    if (tid == 0) {
        volatile unsigned* vgen = &g_bar_gen;
        const unsigned my_gen = *vgen;    // read before arriving
        const unsigned ticket = atomicAdd(&g_bar_count, 1);
        if (ticket == gridDim.x - 1) {
            atomicExch(&g_bar_count, 0);  // reset for next graph replay
            __threadfence();
            atomicAdd(&g_bar_gen, 1);     // release
        } else {
            while (*vgen == my_gen) { }   // plain spin; blocks all resident
        }
    }
    __syncthreads();

    // ================= PHASE B: global top-100 merge =================
    // Only keys cross the barrier; boxes are already in s_kept_box.
    for (int i = tid; i < NCAND; i += TPB)
        s.merge_key[i] = __ldcg(&g_key[b * NCAND + i]);
    __syncthreads();

    if (tid < MAX_PER_CLASS) {
        const int gid = c * MAX_PER_CLASS + tid;
        const unsigned long long myk = s.merge_key[gid];
        const float sc = __uint_as_float((unsigned)(myk >> 32));
        if (sc > SCORE_TH) {              // true exactly when tid < nkeep
            int rank = tid;               // own class: exactly tid greater
            #pragma unroll
            for (int cc = 0; cc < NUM_CLASSES; ++cc) {
                if (cc == c) continue;
                const unsigned long long* arr = s.merge_key + cc * MAX_PER_CLASS;
                int lo = 0, len = MAX_PER_CLASS;
                while (len > 0) {
                    const int half = len >> 1;
                    if (arr[lo + half] > myk) { lo += half + 1; len -= half + 1; }
                    else                      { len = half; }
                }
                rank += lo;
            }
            if (rank < MAX_DET) {
                const float4 bx = s_kept_box[tid];
                float* o = out + ((size_t)b * MAX_DET + rank) * 6;
                o[0] = bx.x; o[1] = bx.y; o[2] = bx.z; o[3] = bx.w;
                o[4] = (float)c;
                o[5] = sc;
            }
        }
    }

    if (c == 0 && tid == 0) {
        int sum = 0;
        #pragma unroll
        for (int i = 0; i < NUM_CLASSES; ++i)
            sum += __ldcg(&g_cnt[b * NUM_CLASSES + i]);
        out[(size_t)B * MAX_DET * 6 + b] = (float)min(sum, MAX_DET);
    }
}

extern "C" void kernel_launch(void* const* d_in, const int* in_sizes, int n_in,
                              void* d_out, int out_size) {
    const float* pred = (const float*)d_in[0];
    int B = in_sizes[0] / (N_BOX * 6);  // expected 4
    nms_fused_kernel<<<B * NUM_CLASSES, TPB>>>(pred, (float*)d_out, B);
}

// round 10
// speedup vs baseline: 1.7500x; 1.3007x over previous
#include <cuda_runtime.h>
#include <cuda_bf16.h>
#include <float.h>

#define NUM_CLASSES 16
#define N_BOX 2048
#define MAXC 256            // max candidates per (image,class); observed ~122 +/- 11
#define NWORD 4             // MAXC/64 keep/mask words
#define TPB 256
#define MAX_PER_CLASS 100
#define MAX_DET 100
#define NCAND (NUM_CLASSES * MAX_PER_CLASS)  // 1600
#define SCORE_TH 0.05f
#define IOU_TH 0.5f

// Scratch (B=4): per-class kept keys only (boxes stay in shared per-block).
//   key = (float_bits(score) << 32) | (0xFFFFFFFF - tag)
// Valid scores > 0 -> float bit pattern preserves order; ~tag breaks ties
// ascending. Each class's 100-slot list is STRICTLY DESCENDING.
__device__ unsigned long long g_key[4 * NCAND];
__device__ int                g_cnt[4 * NUM_CLASSES];

// Grid barrier (replay-safe: count returns to 0 each launch, gen monotone).
__device__ unsigned g_bar_count = 0;
__device__ unsigned g_bar_gen   = 0;

__global__ void __launch_bounds__(TPB)
nms_fused_kernel(const float* __restrict__ pred, float* __restrict__ out, int B) {
    const int task = blockIdx.x;
    const int b = task >> 4;
    const int c = task & 15;
    const int tid = threadIdx.x;
    const int lane = tid & 31;

    __shared__ float4 s_box[MAXC];                 // sorted boxes, 4 KB
    __shared__ float4 s_kept_box[MAX_PER_CLASS];   // compacted kept boxes, 1.6 KB
    __shared__ union {
        struct {
            unsigned long long key[MAXC];          // unsorted keys   (2 KB)
            unsigned long long skey[MAXC];         // sorted keys     (2 KB)
            unsigned long long maskT[MAXC][NWORD]; // SUPPRESSORS j<i (8 KB)
        } a;
        unsigned long long merge_key[NCAND];       // phase B, 12.8 KB
    } s;
    __shared__ unsigned long long s_keepw[NWORD];
    __shared__ unsigned s_ballot[TPB / 32];
    __shared__ int s_cnt;

    if (tid == 0) s_cnt = 0;
    // Zero this image's output rows (one block per image). Ordered before the
    // phase-B scatter writes by the grid barrier.
    if (c == 0) {
        for (int i = tid; i < MAX_DET * 6; i += TPB)
            out[(size_t)b * MAX_DET * 6 + i] = 0.f;
    }

    // ---- filter: prefetch ALL (cls,score) pairs first (MLP=8), then ballot
    //      compaction with one shared atomic per warp-round ----
    const float* base = pred + (size_t)b * N_BOX * 6;
    const float2* cs = (const float2*)base;       // (cls,score) at float2 idx 3n+2
    const float fc = (float)c;
    float2 v[8];
    #pragma unroll
    for (int k = 0; k < 8; ++k)
        v[k] = cs[3 * (tid + k * TPB) + 2];       // independent, front-batched

    __syncthreads();                              // s_cnt=0 visible

    #pragma unroll
    for (int k = 0; k < 8; ++k) {
        const int n = tid + k * TPB;
        const bool hit = (v[k].x == fc) & (v[k].y > SCORE_TH);
        const unsigned m = __ballot_sync(0xffffffffu, hit);
        if (m) {
            const int lead = __ffs(m) - 1;
            int basepos = 0;
            if (lane == lead) basepos = atomicAdd(&s_cnt, __popc(m));
            basepos = __shfl_sync(0xffffffffu, basepos, lead);
            if (hit) {
                const int slot = basepos + __popc(m & ((1u << lane) - 1u));
                if (slot < MAXC)
                    s.a.key[slot] = ((unsigned long long)__float_as_uint(v[k].y) << 32)
                                  | (unsigned long long)(0xFFFFFFFFu - (unsigned)n);
            }
        }
    }
    __syncthreads();
    const int M = min(s_cnt, MAXC);

    // ---- rank sort + fused box gather; idle threads write invalid tag slots ----
    for (int t = tid; t < M + MAX_PER_CLASS; t += TPB) {
        if (t < M) {
            const unsigned long long ki = s.a.key[t];
            int r = 0;
            #pragma unroll 4
            for (int j = 0; j < M; ++j) r += (s.a.key[j] > ki);
            const int n = (int)(0xFFFFFFFFu - (unsigned)(ki & 0xFFFFFFFFull));
            const float2* p = (const float2*)(base + n * 6);
            const float2 p0 = p[0], p1 = p[1];
            s.a.skey[r] = ki;
            s_box[r]    = make_float4(p0.x, p0.y, p1.x, p1.y);
        } else {
            // pre-write all 100 slots as invalid tags; kept entries overwrite
            // later (ordered by the intervening __syncthreads)
            const int k = t - M;
            const int gid = c * MAX_PER_CLASS + k;
            g_key[b * NCAND + gid] =
                (unsigned long long)(0xFFFFFFFFu - (unsigned)gid);
        }
    }
    __syncthreads();

    // ---- TRANSPOSED suppression bitmask: bit j of maskT[i][w] iff j<i and
    //      IoU(i,j) > 0.5 (suppressors of i) ----
    const int NW = (M + 63) >> 6;
    for (int item = tid; item < M * NW; item += TPB) {
        const int i = item / NW;
        const int w = item - i * NW;
        const float4 bi = s_box[i];
        const float areai = (bi.z - bi.x) * (bi.w - bi.y);
        unsigned long long bits = 0ULL;
        const int j0 = w << 6;
        const int jend = min(j0 + 64, i);      // strictly j < i
        for (int j = j0; j < jend; ++j) {
            const float4 bj = s_box[j];
            float iw = fminf(bi.z, bj.z) - fmaxf(bi.x, bj.x);
            float ih = fminf(bi.w, bj.w) - fmaxf(bi.y, bj.y);
            iw = fmaxf(iw, 0.f);
            ih = fmaxf(ih, 0.f);
            const float inter = iw * ih;
            if (inter > 0.f) {
                const float areaj = (bj.z - bj.x) * (bj.w - bj.y);
                const float uni = areai + areaj - inter;
                if (inter / fmaxf(uni, 1e-8f) > IOU_TH)
                    bits |= 1ULL << (j - j0);
            }
        }
        s.a.maskT[i][w] = bits;                // words >= NW never read (keepw=0)
    }
    // init keep words = all valid (bits 0..M-1)
    if (tid < NWORD) {
        const int lo = tid << 6;
        s_keepw[tid] = (M > lo)
                     ? ((M - lo >= 64) ? ~0ULL : ((1ULL << (M - lo)) - 1ULL))
                     : 0ULL;
    }
    __syncthreads();

    // ---- parallel greedy sweep: Jacobi fixpoint of
    //      keep[i] = valid[i] && !exists kept j<i with IoU>th.
    //      Sequential answer is the UNIQUE fixpoint; "no change" <=> fixpoint;
    //      prefix stabilizes by chain depth => terminates (typ. ~3 iters). ----
    bool mykeep = (tid < M);
    for (;;) {
        bool nk = false;
        if (tid < M) {
            const unsigned long long acc =
                  (s.a.maskT[tid][0] & s_keepw[0])
                | (s.a.maskT[tid][1] & s_keepw[1])
                | (s.a.maskT[tid][2] & s_keepw[2])
                | (s.a.maskT[tid][3] & s_keepw[3]);
            nk = (acc == 0ULL);
        }
        const unsigned bal = __ballot_sync(0xffffffffu, nk);
        if (lane == 0) s_ballot[tid >> 5] = bal;
        const int changed = __syncthreads_or((int)(nk != mykeep));  // barrier 1
        mykeep = nk;
        if (tid < NWORD)
            s_keepw[tid] = (unsigned long long)s_ballot[tid * 2]
                         | ((unsigned long long)s_ballot[tid * 2 + 1] << 32);
        __syncthreads();                                            // barrier 2
        if (!changed) break;                   // uniform: no divergence
    }

    // ---- ranks via popcount; emit kept keys + boxes fully parallel ----
    const unsigned long long w0 = s_keepw[0], w1 = s_keepw[1],
                             w2 = s_keepw[2], w3 = s_keepw[3];
    const int total = __popcll(w0) + __popcll(w1) + __popcll(w2) + __popcll(w3);
    const int nkeep = min(total, MAX_PER_CLASS);
    if (tid == 0) g_cnt[task] = nkeep;
    if (mykeep) {
        const int wi = tid >> 6, bit = tid & 63;
        int k = __popcll(s_keepw[wi] & ((1ULL << bit) - 1ULL));
        if (wi > 0) k += __popcll(w0);
        if (wi > 1) k += __popcll(w1);
        if (wi > 2) k += __popcll(w2);
        if (k < MAX_PER_CLASS) {
            const int gid = c * MAX_PER_CLASS + k;
            g_key[b * NCAND + gid] = (s.a.skey[tid] & 0xFFFFFFFF00000000ULL)
                                   | (unsigned long long)(0xFFFFFFFFu - (unsigned)gid);
            s_kept_box[k] = s_box[tid];        // stays in shared across barrier
        }
    }

    // ================= GRID BARRIER (64 co-resident blocks) =================
    __threadfence();
    __syncthreads();
    if (tid == 0) {
        volatile unsigned* vgen = &g_bar_gen;
        const unsigned my_gen = *vgen;    // read before arriving
        const unsigned ticket = atomicAdd(&g_bar_count, 1);
        if (ticket == gridDim.x - 1) {
            atomicExch(&g_bar_count, 0);  // reset for next graph replay
            __threadfence();
            atomicAdd(&g_bar_gen, 1);     // release
        } else {
            while (*vgen == my_gen) { }   // plain spin; blocks all resident
        }
    }
    __syncthreads();

    // ================= PHASE B: global top-100 merge =================
    for (int i = tid; i < NCAND; i += TPB)
        s.merge_key[i] = __ldcg(&g_key[b * NCAND + i]);
    __syncthreads();

    if (tid < MAX_PER_CLASS) {
        const int gid = c * MAX_PER_CLASS + tid;
        const unsigned long long myk = s.merge_key[gid];
        const float sc = __uint_as_float((unsigned)(myk >> 32));
        if (sc > SCORE_TH) {              // true exactly when tid < nkeep
            int rank = tid;               // own class: exactly tid greater
            #pragma unroll
            for (int cc = 0; cc < NUM_CLASSES; ++cc) {
                if (cc == c) continue;
                const unsigned long long* arr = s.merge_key + cc * MAX_PER_CLASS;
                int lo = 0, len = MAX_PER_CLASS;
                while (len > 0) {
                    const int half = len >> 1;
                    if (arr[lo + half] > myk) { lo += half + 1; len -= half + 1; }
                    else                      { len = half; }
                }
                rank += lo;
            }
            if (rank < MAX_DET) {
                const float4 bx = s_kept_box[tid];
                float* o = out + ((size_t)b * MAX_DET + rank) * 6;
                o[0] = bx.x; o[1] = bx.y; o[2] = bx.z; o[3] = bx.w;
                o[4] = (float)c;
                o[5] = sc;
            }
        }
    }

    if (c == 0 && tid == 0) {
        int sum = 0;
        #pragma unroll
        for (int i = 0; i < NUM_CLASSES; ++i)
            sum += __ldcg(&g_cnt[b * NUM_CLASSES + i]);
        out[(size_t)B * MAX_DET * 6 + b] = (float)min(sum, MAX_DET);
    }
}

extern "C" void kernel_launch(void* const* d_in, const int* in_sizes, int n_in,
                              void* d_out, int out_size) {
    const float* pred = (const float*)d_in[0];
    int B = in_sizes[0] / (N_BOX * 6);  // expected 4
    nms_fused_kernel<<<B * NUM_CLASSES, TPB>>>(pred, (float*)d_out, B);
}